// round 6
// baseline (speedup 1.0000x reference)
#include <cuda_runtime.h>
#include <cuda_bf16.h>

// Scratch: __device__ globals (no allocations allowed).
#define MAXN 100352   // >= 100,000 nodes, padded to /4
#define HID  128

__device__ float g_deg[MAXN];   // edge-degree (memset 0; +1 self loop in rsqrt)
__device__ float g_dinv[MAXN];  // (deg+1)^-1/2
__device__ float g_dxv[MAXN];   // dinv * x
__device__ float g_u[MAXN];     // u[c] = sum dinv[r]*x[r]   (seeded w/ self loop)
__device__ float g_t[MAXN];     // t[r] = sum dinv[c]        (seeded w/ self loop)
__device__ float g_A[2];        // A+ , A-   (sum of w*s split by sign of s)
__device__ int   g_ctr;         // last-block counter

// ---------------------------------------------------------------------------
// 1) degree scatter over destinations (8 edges/thread)
__global__ void __launch_bounds__(256) k_deg(const int* __restrict__ col, int E) {
    int t = blockIdx.x * blockDim.x + threadIdx.x;
    int i = t * 8;
    if (i + 7 < E) {
        int c[8];
        *reinterpret_cast<int4*>(c)     = *reinterpret_cast<const int4*>(col + i);
        *reinterpret_cast<int4*>(c + 4) = *reinterpret_cast<const int4*>(col + i + 4);
        #pragma unroll
        for (int j = 0; j < 8; ++j) atomicAdd(&g_deg[c[j]], 1.0f);
    } else if (i < E) {
        for (; i < E; ++i) atomicAdd(&g_deg[col[i]], 1.0f);
    }
}

// 2) dinv = rsqrt(deg+1); dxv = dinv*x; seed u,t with self-loop; zero A & ctr
__global__ void k_dinv(const float* __restrict__ x, int n) {
    int i4 = blockIdx.x * blockDim.x + threadIdx.x;
    int i = i4 * 4;
    if (i + 3 < n) {
        float4 d = *reinterpret_cast<const float4*>(g_deg + i);
        float4 xv = *reinterpret_cast<const float4*>(x + i);
        float4 di, dx;
        di.x = rsqrtf(d.x + 1.0f); di.y = rsqrtf(d.y + 1.0f);
        di.z = rsqrtf(d.z + 1.0f); di.w = rsqrtf(d.w + 1.0f);
        dx.x = di.x * xv.x; dx.y = di.y * xv.y;
        dx.z = di.z * xv.z; dx.w = di.w * xv.w;
        *reinterpret_cast<float4*>(g_dinv + i) = di;
        *reinterpret_cast<float4*>(g_dxv + i)  = dx;
        *reinterpret_cast<float4*>(g_u + i)    = dx;  // self loop: dinv*x
        *reinterpret_cast<float4*>(g_t + i)    = di;  // self loop: dinv
    } else {
        for (; i < n; ++i) {
            float di = rsqrtf(g_deg[i] + 1.0f);
            float dx = di * x[i];
            g_dinv[i] = di; g_dxv[i] = dx; g_u[i] = dx; g_t[i] = di;
        }
    }
    if (i4 == 0) { g_A[0] = 0.0f; g_A[1] = 0.0f; g_ctr = 0; }
}

// 3) edge pass: u[c] += dxv[r]; t[r] += dinv[c]   (12 edges/thread)
#define EPT 12
__global__ void __launch_bounds__(256) k_edge(const int* __restrict__ row,
                                              const int* __restrict__ col, int E) {
    int t = blockIdx.x * blockDim.x + threadIdx.x;
    int i = t * EPT;
    if (i + EPT - 1 < E) {
        int r[EPT], c[EPT];
        #pragma unroll
        for (int q = 0; q < EPT / 4; ++q) {
            *reinterpret_cast<int4*>(r + q * 4) = *reinterpret_cast<const int4*>(row + i + q * 4);
            *reinterpret_cast<int4*>(c + q * 4) = *reinterpret_cast<const int4*>(col + i + q * 4);
        }
        float dx[EPT], dc[EPT];
        #pragma unroll
        for (int j = 0; j < EPT; ++j) {
            dx[j] = __ldg(&g_dxv[r[j]]);
            dc[j] = __ldg(&g_dinv[c[j]]);
        }
        #pragma unroll
        for (int j = 0; j < EPT; ++j) {
            atomicAdd(&g_u[c[j]], dx[j]);
            atomicAdd(&g_t[r[j]], dc[j]);
        }
    } else if (i < E) {
        int iend = min(i + EPT, E);
        for (; i < iend; ++i) {
            int r = row[i], c = col[i];
            atomicAdd(&g_u[c], g_dxv[r]);
            atomicAdd(&g_t[r], g_dinv[c]);
        }
    }
}

// 4) fused: A+/A- reduction over nodes, then last block computes v[k] and the
//    128->400 GEMV.  s_i = dinv*u, w_i = dinv*t.
//    v[k] = W1k * (W1k>0 ? A+ : A-)   when b1k == 0  (exact ReLU factorization)
//    generic-b1 fallback: direct per-node loop (never triggered with b1 = 0).
__global__ void __launch_bounds__(256) k_sred(const float* __restrict__ W1,
                                              const float* __restrict__ b1,
                                              const float* __restrict__ W2,
                                              const float* __restrict__ b2,
                                              float* __restrict__ out,
                                              int n, int od) {
    int tid = threadIdx.x;
    float ap = 0.0f, am = 0.0f;
    int i4 = blockIdx.x * blockDim.x + tid;
    int i = i4 * 4;
    if (i + 3 < n) {
        float4 di = *reinterpret_cast<const float4*>(g_dinv + i);
        float4 u  = *reinterpret_cast<const float4*>(g_u + i);
        float4 tt = *reinterpret_cast<const float4*>(g_t + i);
        float s0 = di.x * u.x, w0 = di.x * tt.x;
        float s1 = di.y * u.y, w1 = di.y * tt.y;
        float s2 = di.z * u.z, w2 = di.z * tt.z;
        float s3 = di.w * u.w, w3 = di.w * tt.w;
        if (s0 > 0.0f) ap += w0 * s0; else am += w0 * s0;
        if (s1 > 0.0f) ap += w1 * s1; else am += w1 * s1;
        if (s2 > 0.0f) ap += w2 * s2; else am += w2 * s2;
        if (s3 > 0.0f) ap += w3 * s3; else am += w3 * s3;
    } else {
        for (; i < n; ++i) {
            float di = g_dinv[i];
            float s = di * g_u[i], w = di * g_t[i];
            if (s > 0.0f) ap += w * s; else am += w * s;
        }
    }
    // warp reduce
    #pragma unroll
    for (int off = 16; off; off >>= 1) {
        ap += __shfl_xor_sync(0xffffffffu, ap, off);
        am += __shfl_xor_sync(0xffffffffu, am, off);
    }
    if ((tid & 31) == 0) {
        atomicAdd(&g_A[0], ap);
        atomicAdd(&g_A[1], am);
    }
    __threadfence();
    __syncthreads();
    __shared__ int sLast;
    if (tid == 0) sLast = (atomicAdd(&g_ctr, 1) == gridDim.x - 1);
    __syncthreads();
    if (!sLast) return;

    // ---- final block: v[k] then GEMV out[o] = (1/n)*sum_k v[k]*W2[k,o] + b2[o]
    __shared__ float vs[HID];
    float Ap = *((volatile float*)&g_A[0]);
    float Am = *((volatile float*)&g_A[1]);
    if (tid < HID) {
        float w1k = W1[tid];
        float b1k = b1[tid];
        float v;
        if (b1k == 0.0f) {
            v = w1k * (w1k > 0.0f ? Ap : Am);   // exact when b1k == 0
        } else {
            // generic fallback (not hit with these inputs): direct loop
            v = 0.0f;
            for (int q = 0; q < n; ++q) {
                float di = g_dinv[q];
                float s = di * g_u[q], w = di * g_t[q];
                v += w * fmaxf(s * w1k + b1k, 0.0f);
            }
        }
        vs[tid] = v;
    }
    __syncthreads();
    float inv_n = 1.0f / (float)n;
    int od4 = od >> 2;
    for (int o4 = tid; o4 < od4; o4 += 256) {
        float4 a = make_float4(0.f, 0.f, 0.f, 0.f);
        #pragma unroll 8
        for (int kk = 0; kk < HID; ++kk) {
            float4 wrow = *reinterpret_cast<const float4*>(W2 + kk * od + o4 * 4);
            float vk = vs[kk];
            a.x += vk * wrow.x; a.y += vk * wrow.y;
            a.z += vk * wrow.z; a.w += vk * wrow.w;
        }
        int o = o4 * 4;
        out[o + 0] = a.x * inv_n + b2[o + 0];
        out[o + 1] = a.y * inv_n + b2[o + 1];
        out[o + 2] = a.z * inv_n + b2[o + 2];
        out[o + 3] = a.w * inv_n + b2[o + 3];
    }
    for (int o = od4 * 4 + tid; o < od; o += 256) {  // tail (od % 4 != 0)
        float a = 0.0f;
        for (int kk = 0; kk < HID; ++kk) a += vs[kk] * W2[kk * od + o];
        out[o] = a * inv_n + b2[o];
    }
}

// ---------------------------------------------------------------------------
extern "C" void kernel_launch(void* const* d_in, const int* in_sizes, int n_in,
                              void* d_out, int out_size) {
    const float* x   = (const float*)d_in[0];   // [N]
    const int*   ei  = (const int*)d_in[1];     // [2, E] row-major
    const float* W1  = (const float*)d_in[2];   // [128]
    const float* b1  = (const float*)d_in[3];   // [128]
    const float* W2  = (const float*)d_in[4];   // [128, OUT]
    const float* b2  = (const float*)d_in[5];   // [OUT]
    float* out = (float*)d_out;

    int N = in_sizes[0];
    int E = in_sizes[1] / 2;
    int OD = in_sizes[5];
    const int* row = ei;
    const int* col = ei + E;

    void* degp = nullptr;
    cudaGetSymbolAddress(&degp, g_deg);
    cudaMemsetAsync(degp, 0, (size_t)N * sizeof(float));

    int tb = 256;
    int nt8 = (E + 7) / 8;
    k_deg<<<(nt8 + tb - 1) / tb, tb>>>(col, E);

    int n4 = (N + 3) / 4;
    k_dinv<<<(n4 + tb - 1) / tb, tb>>>(x, N);

    int ntE = (E + EPT - 1) / EPT;
    k_edge<<<(ntE + tb - 1) / tb, tb>>>(row, col, E);

    k_sred<<<(n4 + tb - 1) / tb, tb>>>(W1, b1, W2, b2, out, N, OD);
}

// round 7
// speedup vs baseline: 1.1815x; 1.1815x over previous
#include <cuda_runtime.h>
#include <cuda_bf16.h>

// Scratch: __device__ globals (no allocations allowed).
#define MAXN 100352   // >= 100,000 nodes, padded to /4
#define HID  128

__device__ float g_deg[MAXN];   // edge-degree (memset 0; +1 self loop in rsqrt)
__device__ float g_dinv[MAXN];  // (deg+1)^-1/2
__device__ float g_dxv[MAXN];   // dinv * x
__device__ float g_u[MAXN];     // u[c] = sum dinv[r]*x[r]   (seeded w/ self loop)
__device__ float g_t[MAXN];     // t[r] = sum dinv[c]        (seeded w/ self loop)
__device__ float g_A[2];        // A+ , A-   (sum of w*s split by sign of s)

// ---------------------------------------------------------------------------
// 1) degree scatter over destinations (8 edges/thread)
__global__ void __launch_bounds__(256) k_deg(const int* __restrict__ col, int E) {
    int t = blockIdx.x * blockDim.x + threadIdx.x;
    int i = t * 8;
    if (i + 7 < E) {
        int c[8];
        *reinterpret_cast<int4*>(c)     = *reinterpret_cast<const int4*>(col + i);
        *reinterpret_cast<int4*>(c + 4) = *reinterpret_cast<const int4*>(col + i + 4);
        #pragma unroll
        for (int j = 0; j < 8; ++j) atomicAdd(&g_deg[c[j]], 1.0f);
    } else if (i < E) {
        for (; i < E; ++i) atomicAdd(&g_deg[col[i]], 1.0f);
    }
}

// 2) dinv = rsqrt(deg+1); dxv = dinv*x; seed u,t with self-loop; zero A
__global__ void k_dinv(const float* __restrict__ x, int n) {
    int i4 = blockIdx.x * blockDim.x + threadIdx.x;
    int i = i4 * 4;
    if (i + 3 < n) {
        float4 d = *reinterpret_cast<const float4*>(g_deg + i);
        float4 xv = *reinterpret_cast<const float4*>(x + i);
        float4 di, dx;
        di.x = rsqrtf(d.x + 1.0f); di.y = rsqrtf(d.y + 1.0f);
        di.z = rsqrtf(d.z + 1.0f); di.w = rsqrtf(d.w + 1.0f);
        dx.x = di.x * xv.x; dx.y = di.y * xv.y;
        dx.z = di.z * xv.z; dx.w = di.w * xv.w;
        *reinterpret_cast<float4*>(g_dinv + i) = di;
        *reinterpret_cast<float4*>(g_dxv + i)  = dx;
        *reinterpret_cast<float4*>(g_u + i)    = dx;  // self loop: dinv*x
        *reinterpret_cast<float4*>(g_t + i)    = di;  // self loop: dinv
    } else {
        for (; i < n; ++i) {
            float di = rsqrtf(g_deg[i] + 1.0f);
            float dx = di * x[i];
            g_dinv[i] = di; g_dxv[i] = dx; g_u[i] = dx; g_t[i] = di;
        }
    }
    if (i4 == 0) { g_A[0] = 0.0f; g_A[1] = 0.0f; }
}

// 3) edge pass: u[c] += dxv[r]; t[r] += dinv[c]   (12 edges/thread)
#define EPT 12
__global__ void __launch_bounds__(256) k_edge(const int* __restrict__ row,
                                              const int* __restrict__ col, int E) {
    int t = blockIdx.x * blockDim.x + threadIdx.x;
    int i = t * EPT;
    if (i + EPT - 1 < E) {
        int r[EPT], c[EPT];
        #pragma unroll
        for (int q = 0; q < EPT / 4; ++q) {
            *reinterpret_cast<int4*>(r + q * 4) = *reinterpret_cast<const int4*>(row + i + q * 4);
            *reinterpret_cast<int4*>(c + q * 4) = *reinterpret_cast<const int4*>(col + i + q * 4);
        }
        float dx[EPT], dc[EPT];
        #pragma unroll
        for (int j = 0; j < EPT; ++j) {
            dx[j] = __ldg(&g_dxv[r[j]]);
            dc[j] = __ldg(&g_dinv[c[j]]);
        }
        #pragma unroll
        for (int j = 0; j < EPT; ++j) {
            atomicAdd(&g_u[c[j]], dx[j]);
            atomicAdd(&g_t[r[j]], dc[j]);
        }
    } else if (i < E) {
        int iend = min(i + EPT, E);
        for (; i < iend; ++i) {
            int r = row[i], c = col[i];
            atomicAdd(&g_u[c], g_dxv[r]);
            atomicAdd(&g_t[r], g_dinv[c]);
        }
    }
}

// 4) A+/A- reduction over nodes.  s_i = dinv*u, w_i = dinv*t.
//    No fence, no counter — completion ordering comes from the kernel boundary.
__global__ void __launch_bounds__(256) k_sred(int n) {
    int tid = threadIdx.x;
    float ap = 0.0f, am = 0.0f;
    int i4 = blockIdx.x * blockDim.x + tid;
    int i = i4 * 4;
    if (i + 3 < n) {
        float4 di = *reinterpret_cast<const float4*>(g_dinv + i);
        float4 u  = *reinterpret_cast<const float4*>(g_u + i);
        float4 tt = *reinterpret_cast<const float4*>(g_t + i);
        float s0 = di.x * u.x, w0 = di.x * tt.x;
        float s1 = di.y * u.y, w1 = di.y * tt.y;
        float s2 = di.z * u.z, w2 = di.z * tt.z;
        float s3 = di.w * u.w, w3 = di.w * tt.w;
        if (s0 > 0.0f) ap += w0 * s0; else am += w0 * s0;
        if (s1 > 0.0f) ap += w1 * s1; else am += w1 * s1;
        if (s2 > 0.0f) ap += w2 * s2; else am += w2 * s2;
        if (s3 > 0.0f) ap += w3 * s3; else am += w3 * s3;
    } else {
        for (; i < n; ++i) {
            float di = g_dinv[i];
            float s = di * g_u[i], w = di * g_t[i];
            if (s > 0.0f) ap += w * s; else am += w * s;
        }
    }
    #pragma unroll
    for (int off = 16; off; off >>= 1) {
        ap += __shfl_xor_sync(0xffffffffu, ap, off);
        am += __shfl_xor_sync(0xffffffffu, am, off);
    }
    if ((tid & 31) == 0) {
        atomicAdd(&g_A[0], ap);
        atomicAdd(&g_A[1], am);
    }
}

// 5) v[k] = W1k * (W1k>0 ? A+ : A-)   (exact when b1k == 0; fallback otherwise),
//    then out[o] = (1/n)*sum_k v[k]*W2[k,o] + b2[o].  Coalesced over o.
__global__ void __launch_bounds__(256) k_gemv(const float* __restrict__ W1,
                                              const float* __restrict__ b1,
                                              const float* __restrict__ W2,
                                              const float* __restrict__ b2,
                                              float* __restrict__ out,
                                              int n, int od) {
    __shared__ float vs[HID];
    int tid = threadIdx.x;
    if (tid < HID) {
        float Ap = g_A[0];
        float Am = g_A[1];
        float w1k = W1[tid];
        float b1k = b1[tid];
        float v;
        if (b1k == 0.0f) {
            v = w1k * (w1k > 0.0f ? Ap : Am);   // exact ReLU factorization
        } else {
            // generic fallback (never hit with b1 = 0): direct per-node loop
            v = 0.0f;
            for (int q = 0; q < n; ++q) {
                float di = g_dinv[q];
                float s = di * g_u[q], w = di * g_t[q];
                v += w * fmaxf(s * w1k + b1k, 0.0f);
            }
        }
        vs[tid] = v;
    }
    __syncthreads();
    int o = blockIdx.x * blockDim.x + tid;
    if (o >= od) return;
    float inv_n = 1.0f / (float)n;
    float a = 0.0f;
    #pragma unroll 8
    for (int kk = 0; kk < HID; ++kk) {
        a += vs[kk] * W2[kk * od + o];   // coalesced: consecutive threads, consecutive o
    }
    out[o] = a * inv_n + b2[o];
}

// ---------------------------------------------------------------------------
extern "C" void kernel_launch(void* const* d_in, const int* in_sizes, int n_in,
                              void* d_out, int out_size) {
    const float* x   = (const float*)d_in[0];   // [N]
    const int*   ei  = (const int*)d_in[1];     // [2, E] row-major
    const float* W1  = (const float*)d_in[2];   // [128]
    const float* b1  = (const float*)d_in[3];   // [128]
    const float* W2  = (const float*)d_in[4];   // [128, OUT]
    const float* b2  = (const float*)d_in[5];   // [OUT]
    float* out = (float*)d_out;

    int N = in_sizes[0];
    int E = in_sizes[1] / 2;
    int OD = in_sizes[5];
    const int* row = ei;
    const int* col = ei + E;

    void* degp = nullptr;
    cudaGetSymbolAddress(&degp, g_deg);
    cudaMemsetAsync(degp, 0, (size_t)N * sizeof(float));

    int tb = 256;
    int nt8 = (E + 7) / 8;
    k_deg<<<(nt8 + tb - 1) / tb, tb>>>(col, E);

    int n4 = (N + 3) / 4;
    k_dinv<<<(n4 + tb - 1) / tb, tb>>>(x, N);

    int ntE = (E + EPT - 1) / EPT;
    k_edge<<<(ntE + tb - 1) / tb, tb>>>(row, col, E);

    k_sred<<<(n4 + tb - 1) / tb, tb>>>(N);

    k_gemv<<<(OD + tb - 1) / tb, tb>>>(W1, b1, W2, b2, out, N, OD);
}